// round 11
// baseline (speedup 1.0000x reference)
#include <cuda_runtime.h>
#include <cuda_bf16.h>

// DetectionLoss, single fused kernel, v9 (v8 + warp-autonomous tail).
// Grid (64 batches x 3 scales) x 64 threads, one target per thread.
// Sparse evaluation, register-resident collision scan. After the scan each
// WARP reduces and REDGs its own partials (no second __syncthreads, no smem
// bounce); completion = per-batch counter (6 warp-arrivals) -> root (64).

#define NCH   11
#define NCLS  6
#define NT    60
#define NB    64

__device__ float    g_sum[12];         // [scale*4 + {cls,iou,inner,np}] one line
__device__ unsigned g_done1[NB][32];   // per-batch counter, 128B padded
__device__ unsigned g_done2;           // root counter (NB arrivals)

__device__ __forceinline__ float iou_scaled(
    float px, float py, float pw, float ph,
    float tx, float ty, float tw, float th, float sc)
{
    float pw2 = pw * sc * 0.5f, ph2 = ph * sc * 0.5f;
    float tw2 = tw * sc * 0.5f, th2 = th * sc * 0.5f;
    float x11 = px - pw2, x12 = px + pw2;
    float y11 = py - ph2, y12 = py + ph2;
    float x21 = tx - tw2, x22 = tx + tw2;
    float y21 = ty - th2, y22 = ty + th2;
    float iw = fmaxf(fminf(x12, x22) - fmaxf(x11, x21), 0.0f);
    float ih = fmaxf(fminf(y12, y22) - fmaxf(y11, y21), 0.0f);
    float inter = iw * ih;
    float a1 = (x12 - x11) * (y12 - y11);
    float a2 = (x22 - x21) * (y22 - y21);
    return inter / (a1 + a2 - inter + 1e-7f);
}

__global__ void __launch_bounds__(64, 16) dl_fused_kernel(
    const float* __restrict__ p3,
    const float* __restrict__ p4,
    const float* __restrict__ p5,
    const int*   __restrict__ tcls,
    const float* __restrict__ tbox,
    float*       __restrict__ out)
{
    const int b   = blockIdx.x;
    const int s   = blockIdx.y;
    const int tid = threadIdx.x;

    const float* pred;
    int W;
    if      (s == 0) { pred = p3; W = 160; }
    else if (s == 1) { pred = p4; W = 80;  }
    else             { pred = p5; W = 40;  }

    __shared__ int4 s_pk4[15];      // packed (cell<<6)|cls, 60 entries

    float tx = 0.f, ty = 0.f, tw = 0.f, th = 0.f;
    int   cell = -1;
    float z[NCLS], px = 0.f, py = 0.f, pw = 0.f, ph = 0.f;

    if (tid < NT) {
        int   cls = tcls[b * NT + tid];
        float4 bx = reinterpret_cast<const float4*>(tbox)[b * NT + tid];
        tx = bx.x; ty = bx.y; tw = bx.z; th = bx.w;
        int gx = (int)(tx * (float)W); gx = min(max(gx, 0), W - 1);
        int gy = (int)(ty * (float)W); gy = min(max(gy, 0), W - 1);
        cell = gy * W + gx;
        reinterpret_cast<int*>(&s_pk4[0])[tid] = (cell << 6) | cls;

        // 32-bit offsets (max index < 2^25); all 10 scattered loads issued
        // up front (MLP=10) so the DRAM/L2 latency overlaps the scan.
        const int HW = W * W;
        const float* base = pred + b * NCH * HW + cell;
        #pragma unroll
        for (int c = 0; c < NCLS; ++c) z[c] = __ldg(base + c * HW);
        px = __ldg(base + 7  * HW);
        py = __ldg(base + 8  * HW);
        pw = __ldg(base + 9  * HW);
        ph = __ldg(base + 10 * HW);
    }
    __syncthreads();   // s_pk4 spans both warps; scan reads all 60 entries

    float cls_p = 0.0f, iou_p = 0.0f, inner_p = 0.0f, np = 0.0f;

    if (tid < NT) {
        // Register-resident scan over all 60 packed entries (broadcast LDS.128).
        const int cellsh = cell << 6;
        unsigned cm  = 0u;   // union of one-hot classes at this cell
        int      bad = 0;    // some later target claims this cell
        #pragma unroll
        for (int i = 0; i < 15; ++i) {
            int4 q = s_pk4[i];
            int idx = i * 4;
            if (((q.x ^ cellsh) & ~63) == 0) { cm |= 1u << (q.x & 63); bad |= (idx + 0 > tid); }
            if (((q.y ^ cellsh) & ~63) == 0) { cm |= 1u << (q.y & 63); bad |= (idx + 1 > tid); }
            if (((q.z ^ cellsh) & ~63) == 0) { cm |= 1u << (q.z & 63); bad |= (idx + 2 > tid); }
            if (((q.w ^ cellsh) & ~63) == 0) { cm |= 1u << (q.w & 63); bad |= (idx + 3 > tid); }
        }

        if (!bad) {   // owner = last target mapping to this cell
            float bce = 0.0f;
            #pragma unroll
            for (int c = 0; c < NCLS; ++c) {
                float tt = ((cm >> c) & 1u) ? 1.0f : 0.0f;
                bce += fmaxf(z[c], 0.0f) - z[c] * tt
                     + __logf(1.0f + __expf(-fabsf(z[c])));
            }
            float iou   = iou_scaled(px, py, pw, ph, tx, ty, tw, th, 1.0f);
            float inner = iou_scaled(px, py, pw, ph, tx, ty, tw, th, 0.7f);
            cls_p = bce;  iou_p = 1.0f - iou;  inner_p = 1.0f - inner;  np = 1.0f;
        }
    }

    // Warp-autonomous tail: shfl reduce, lane 0 REDGs its warp's partials
    // straight into the 12 contiguous sums. No cross-warp sync needed.
    #pragma unroll
    for (int o = 16; o > 0; o >>= 1) {
        cls_p   += __shfl_down_sync(0xffffffffu, cls_p,   o);
        iou_p   += __shfl_down_sync(0xffffffffu, iou_p,   o);
        inner_p += __shfl_down_sync(0xffffffffu, inner_p, o);
        np      += __shfl_down_sync(0xffffffffu, np,      o);
    }

    if ((tid & 31) == 0) {
        atomicAdd(&g_sum[s * 4 + 0], cls_p);
        atomicAdd(&g_sum[s * 4 + 1], iou_p);
        atomicAdd(&g_sum[s * 4 + 2], inner_p);
        atomicAdd(&g_sum[s * 4 + 3], np);
        __threadfence();

        // Hierarchical completion: per-batch counter (6 warp-arrivals,
        // 64 counters in parallel) -> root counter (64 arrivals).
        unsigned d1 = atomicAdd(&g_done1[b][0], 1u);
        if (d1 == 5u) {                       // batch-last warp
            atomicExch(&g_done1[b][0], 0u);   // reset own counter (we are 6th)
            unsigned d2 = atomicAdd(&g_done2, 1u);
            if (d2 == NB - 1) {
                // Every warp fenced its REDGs before its counter bumps; final
                // root count observed => the 12 sums are complete in L2
                // (one cache line -> a single round trip).
                float m[12];
                #pragma unroll
                for (int k = 0; k < 12; ++k)
                    m[k] = ((const volatile float*)g_sum)[k];

                float cls_total = 0.0f, box_total = 0.0f;
                #pragma unroll
                for (int k2 = 0; k2 < 3; ++k2) {
                    float inv = 1.0f / (m[k2 * 4 + 3] + 1e-8f);
                    cls_total += m[k2 * 4 + 0] * inv;
                    // box = 0.5*iou + 0.5*(0.5*iou + 0.5*inner)
                    box_total += 0.75f * (m[k2 * 4 + 1] * inv)
                               + 0.25f * (m[k2 * 4 + 2] * inv);
                }
                cls_total *= (1.0f / 3.0f);
                box_total *= (1.0f / 3.0f);
                out[0] = 0.5f * cls_total + 7.5f * box_total;  // CLS_W, BOX_W
                out[1] = cls_total;
                out[2] = box_total;

                // Reset for next graph replay (kernel-end membar publishes).
                #pragma unroll
                for (int k = 0; k < 12; ++k) g_sum[k] = 0.0f;
                g_done2 = 0u;
            }
        }
    }
}

extern "C" void kernel_launch(void* const* d_in, const int* in_sizes, int n_in,
                              void* d_out, int out_size)
{
    const float* p3   = (const float*)d_in[0];
    const float* p4   = (const float*)d_in[1];
    const float* p5   = (const float*)d_in[2];
    const int*   tcls = (const int*)  d_in[3];
    const float* tbox = (const float*)d_in[4];
    float*       out  = (float*)d_out;

    dim3 grid(NB, 3);
    dl_fused_kernel<<<grid, 64>>>(p3, p4, p5, tcls, tbox, out);
}

// round 12
// speedup vs baseline: 1.1906x; 1.1906x over previous
#include <cuda_runtime.h>
#include <cuda_bf16.h>

// DetectionLoss, single fused kernel, v10 (= v8 best + vectorized REDG).
// Grid (64 batches x 3 scales) x 64 threads, one target per thread.
// Sparse evaluation, register-resident collision scan, hierarchical
// completion counters. Each block's leader folds its 4 partial sums into a
// single red.global.add.v4.f32 (sm_90+), cutting same-line atomic ops 4x.

#define NCH   11
#define NCLS  6
#define NT    60
#define NB    64

__device__ __align__(16) float g_sum[12];   // [scale*4 + {cls,iou,inner,np}]
__device__ unsigned g_done1[NB][32];        // per-batch counter, 128B padded
__device__ unsigned g_done2;                // root counter (NB arrivals)

__device__ __forceinline__ float iou_scaled(
    float px, float py, float pw, float ph,
    float tx, float ty, float tw, float th, float sc)
{
    float pw2 = pw * sc * 0.5f, ph2 = ph * sc * 0.5f;
    float tw2 = tw * sc * 0.5f, th2 = th * sc * 0.5f;
    float x11 = px - pw2, x12 = px + pw2;
    float y11 = py - ph2, y12 = py + ph2;
    float x21 = tx - tw2, x22 = tx + tw2;
    float y21 = ty - th2, y22 = ty + th2;
    float iw = fmaxf(fminf(x12, x22) - fmaxf(x11, x21), 0.0f);
    float ih = fmaxf(fminf(y12, y22) - fmaxf(y11, y21), 0.0f);
    float inter = iw * ih;
    float a1 = (x12 - x11) * (y12 - y11);
    float a2 = (x22 - x21) * (y22 - y21);
    return inter / (a1 + a2 - inter + 1e-7f);
}

__global__ void __launch_bounds__(64, 16) dl_fused_kernel(
    const float* __restrict__ p3,
    const float* __restrict__ p4,
    const float* __restrict__ p5,
    const int*   __restrict__ tcls,
    const float* __restrict__ tbox,
    float*       __restrict__ out)
{
    const int b   = blockIdx.x;
    const int s   = blockIdx.y;
    const int tid = threadIdx.x;

    const float* pred;
    int W;
    if      (s == 0) { pred = p3; W = 160; }
    else if (s == 1) { pred = p4; W = 80;  }
    else             { pred = p5; W = 40;  }

    __shared__ int4  s_pk4[15];      // packed (cell<<6)|cls, 60 entries
    __shared__ float s_red[2][4];    // 2-warp partials

    float tx = 0.f, ty = 0.f, tw = 0.f, th = 0.f;
    int   cell = -1;
    float z[NCLS], px = 0.f, py = 0.f, pw = 0.f, ph = 0.f;

    if (tid < NT) {
        int   cls = tcls[b * NT + tid];
        float4 bx = reinterpret_cast<const float4*>(tbox)[b * NT + tid];
        tx = bx.x; ty = bx.y; tw = bx.z; th = bx.w;
        int gx = (int)(tx * (float)W); gx = min(max(gx, 0), W - 1);
        int gy = (int)(ty * (float)W); gy = min(max(gy, 0), W - 1);
        cell = gy * W + gx;
        reinterpret_cast<int*>(&s_pk4[0])[tid] = (cell << 6) | cls;

        // 32-bit offsets (max index < 2^25); all 10 scattered loads issued
        // up front (MLP=10) so the DRAM/L2 latency overlaps the scan.
        const int HW = W * W;
        const float* base = pred + b * NCH * HW + cell;
        #pragma unroll
        for (int c = 0; c < NCLS; ++c) z[c] = __ldg(base + c * HW);
        px = __ldg(base + 7  * HW);
        py = __ldg(base + 8  * HW);
        pw = __ldg(base + 9  * HW);
        ph = __ldg(base + 10 * HW);
    }
    __syncthreads();

    float cls_p = 0.0f, iou_p = 0.0f, inner_p = 0.0f, np = 0.0f;

    if (tid < NT) {
        // Register-resident scan over all 60 packed entries (broadcast LDS.128).
        const int cellsh = cell << 6;
        unsigned cm  = 0u;   // union of one-hot classes at this cell
        int      bad = 0;    // some later target claims this cell
        #pragma unroll
        for (int i = 0; i < 15; ++i) {
            int4 q = s_pk4[i];
            int idx = i * 4;
            if (((q.x ^ cellsh) & ~63) == 0) { cm |= 1u << (q.x & 63); bad |= (idx + 0 > tid); }
            if (((q.y ^ cellsh) & ~63) == 0) { cm |= 1u << (q.y & 63); bad |= (idx + 1 > tid); }
            if (((q.z ^ cellsh) & ~63) == 0) { cm |= 1u << (q.z & 63); bad |= (idx + 2 > tid); }
            if (((q.w ^ cellsh) & ~63) == 0) { cm |= 1u << (q.w & 63); bad |= (idx + 3 > tid); }
        }

        if (!bad) {   // owner = last target mapping to this cell
            float bce = 0.0f;
            #pragma unroll
            for (int c = 0; c < NCLS; ++c) {
                float tt = ((cm >> c) & 1u) ? 1.0f : 0.0f;
                bce += fmaxf(z[c], 0.0f) - z[c] * tt
                     + __logf(1.0f + __expf(-fabsf(z[c])));
            }
            float iou   = iou_scaled(px, py, pw, ph, tx, ty, tw, th, 1.0f);
            float inner = iou_scaled(px, py, pw, ph, tx, ty, tw, th, 0.7f);
            cls_p = bce;  iou_p = 1.0f - iou;  inner_p = 1.0f - inner;  np = 1.0f;
        }
    }

    // Warp shfl reduce, combine the 2 warps in smem.
    #pragma unroll
    for (int o = 16; o > 0; o >>= 1) {
        cls_p   += __shfl_down_sync(0xffffffffu, cls_p,   o);
        iou_p   += __shfl_down_sync(0xffffffffu, iou_p,   o);
        inner_p += __shfl_down_sync(0xffffffffu, inner_p, o);
        np      += __shfl_down_sync(0xffffffffu, np,      o);
    }
    const int warp = tid >> 5;
    if ((tid & 31) == 0) {
        s_red[warp][0] = cls_p;  s_red[warp][1] = iou_p;
        s_red[warp][2] = inner_p; s_red[warp][3] = np;
    }
    __syncthreads();

    // Leader: ONE vector reduction (red.global.add.v4.f32) for all 4
    // partials -> 192 total atomic ops on the hot line instead of 768.
    // Then hierarchical completion: per-batch counter (3 arrivals) -> root.
    if (tid == 0) {
        float v0 = s_red[0][0] + s_red[1][0];
        float v1 = s_red[0][1] + s_red[1][1];
        float v2 = s_red[0][2] + s_red[1][2];
        float v3 = s_red[0][3] + s_red[1][3];
        asm volatile("red.global.add.v4.f32 [%0], {%1, %2, %3, %4};"
                     :: "l"(&g_sum[s * 4]), "f"(v0), "f"(v1), "f"(v2), "f"(v3)
                     : "memory");
        __threadfence();

        int lastflag = 0;
        unsigned d1 = atomicAdd(&g_done1[b][0], 1u);
        if (d1 == 2u) {                       // batch-last block
            atomicExch(&g_done1[b][0], 0u);   // reset own counter (we are 3rd)
            unsigned d2 = atomicAdd(&g_done2, 1u);
            lastflag = (d2 == NB - 1);
        }

        if (lastflag) {
            // Every block fenced its reduction before its counter bumps;
            // final root count observed => the 12 sums are complete in L2
            // (one cache line -> a single round trip).
            float m[12];
            #pragma unroll
            for (int k = 0; k < 12; ++k)
                m[k] = ((const volatile float*)g_sum)[k];

            float cls_total = 0.0f, box_total = 0.0f;
            #pragma unroll
            for (int k2 = 0; k2 < 3; ++k2) {
                float inv = 1.0f / (m[k2 * 4 + 3] + 1e-8f);
                cls_total += m[k2 * 4 + 0] * inv;
                // box = 0.5*iou + 0.5*(0.5*iou + 0.5*inner)
                box_total += 0.75f * (m[k2 * 4 + 1] * inv)
                           + 0.25f * (m[k2 * 4 + 2] * inv);
            }
            cls_total *= (1.0f / 3.0f);
            box_total *= (1.0f / 3.0f);
            out[0] = 0.5f * cls_total + 7.5f * box_total;  // CLS_W, BOX_W
            out[1] = cls_total;
            out[2] = box_total;

            // Reset for next graph replay (kernel-end membar publishes).
            #pragma unroll
            for (int k = 0; k < 12; ++k) g_sum[k] = 0.0f;
            g_done2 = 0u;
        }
    }
}

extern "C" void kernel_launch(void* const* d_in, const int* in_sizes, int n_in,
                              void* d_out, int out_size)
{
    const float* p3   = (const float*)d_in[0];
    const float* p4   = (const float*)d_in[1];
    const float* p5   = (const float*)d_in[2];
    const int*   tcls = (const int*)  d_in[3];
    const float* tbox = (const float*)d_in[4];
    float*       out  = (float*)d_out;

    dim3 grid(NB, 3);
    dl_fused_kernel<<<grid, 64>>>(p3, p4, p5, tcls, tbox, out);
}

// round 13
// speedup vs baseline: 1.2214x; 1.0258x over previous
#include <cuda_runtime.h>
#include <cuda_bf16.h>

// DetectionLoss, single fused kernel, v11 (= v10 + release/acquire tail).
// Grid (64 batches x 3 scales) x 64 threads, one target per thread.
// Sparse evaluation, register-resident collision scan. Block leader folds
// its 4 partials into one red.global.add.v4.f32; completion uses
// acq_rel counter atomics (release publishes the red, acquire observes all
// published sums) -- no MEMBAR.ALL.GPU on the leader path.

#define NCH   11
#define NCLS  6
#define NT    60
#define NB    64

__device__ __align__(16) float g_sum[12];   // [scale*4 + {cls,iou,inner,np}]
__device__ unsigned g_done1[NB][32];        // per-batch counter, 128B padded
__device__ unsigned g_done2;                // root counter (NB arrivals)

__device__ __forceinline__ unsigned atom_add_acq_rel(unsigned* p, unsigned v)
{
    unsigned old;
    asm volatile("atom.acq_rel.gpu.global.add.u32 %0, [%1], %2;"
                 : "=r"(old) : "l"(p), "r"(v) : "memory");
    return old;
}

__device__ __forceinline__ float iou_scaled(
    float px, float py, float pw, float ph,
    float tx, float ty, float tw, float th, float sc)
{
    float pw2 = pw * sc * 0.5f, ph2 = ph * sc * 0.5f;
    float tw2 = tw * sc * 0.5f, th2 = th * sc * 0.5f;
    float x11 = px - pw2, x12 = px + pw2;
    float y11 = py - ph2, y12 = py + ph2;
    float x21 = tx - tw2, x22 = tx + tw2;
    float y21 = ty - th2, y22 = ty + th2;
    float iw = fmaxf(fminf(x12, x22) - fmaxf(x11, x21), 0.0f);
    float ih = fmaxf(fminf(y12, y22) - fmaxf(y11, y21), 0.0f);
    float inter = iw * ih;
    float a1 = (x12 - x11) * (y12 - y11);
    float a2 = (x22 - x21) * (y22 - y21);
    return inter / (a1 + a2 - inter + 1e-7f);
}

__global__ void __launch_bounds__(64, 16) dl_fused_kernel(
    const float* __restrict__ p3,
    const float* __restrict__ p4,
    const float* __restrict__ p5,
    const int*   __restrict__ tcls,
    const float* __restrict__ tbox,
    float*       __restrict__ out)
{
    const int b   = blockIdx.x;
    const int s   = blockIdx.y;
    const int tid = threadIdx.x;

    const float* pred;
    int W;
    if      (s == 0) { pred = p3; W = 160; }
    else if (s == 1) { pred = p4; W = 80;  }
    else             { pred = p5; W = 40;  }

    __shared__ int4  s_pk4[15];      // packed (cell<<6)|cls, 60 entries
    __shared__ float s_red[2][4];    // 2-warp partials

    float tx = 0.f, ty = 0.f, tw = 0.f, th = 0.f;
    int   cell = -1;
    float z[NCLS], px = 0.f, py = 0.f, pw = 0.f, ph = 0.f;

    if (tid < NT) {
        int   cls = tcls[b * NT + tid];
        float4 bx = reinterpret_cast<const float4*>(tbox)[b * NT + tid];
        tx = bx.x; ty = bx.y; tw = bx.z; th = bx.w;
        int gx = (int)(tx * (float)W); gx = min(max(gx, 0), W - 1);
        int gy = (int)(ty * (float)W); gy = min(max(gy, 0), W - 1);
        cell = gy * W + gx;
        reinterpret_cast<int*>(&s_pk4[0])[tid] = (cell << 6) | cls;

        // 32-bit offsets (max index < 2^25); all 10 scattered loads issued
        // up front (MLP=10) so the DRAM/L2 latency overlaps the scan.
        const int HW = W * W;
        const float* base = pred + b * NCH * HW + cell;
        #pragma unroll
        for (int c = 0; c < NCLS; ++c) z[c] = __ldg(base + c * HW);
        px = __ldg(base + 7  * HW);
        py = __ldg(base + 8  * HW);
        pw = __ldg(base + 9  * HW);
        ph = __ldg(base + 10 * HW);
    }
    __syncthreads();

    float cls_p = 0.0f, iou_p = 0.0f, inner_p = 0.0f, np = 0.0f;

    if (tid < NT) {
        // Register-resident scan over all 60 packed entries (broadcast LDS.128).
        const int cellsh = cell << 6;
        unsigned cm  = 0u;   // union of one-hot classes at this cell
        int      bad = 0;    // some later target claims this cell
        #pragma unroll
        for (int i = 0; i < 15; ++i) {
            int4 q = s_pk4[i];
            int idx = i * 4;
            if (((q.x ^ cellsh) & ~63) == 0) { cm |= 1u << (q.x & 63); bad |= (idx + 0 > tid); }
            if (((q.y ^ cellsh) & ~63) == 0) { cm |= 1u << (q.y & 63); bad |= (idx + 1 > tid); }
            if (((q.z ^ cellsh) & ~63) == 0) { cm |= 1u << (q.z & 63); bad |= (idx + 2 > tid); }
            if (((q.w ^ cellsh) & ~63) == 0) { cm |= 1u << (q.w & 63); bad |= (idx + 3 > tid); }
        }

        if (!bad) {   // owner = last target mapping to this cell
            float bce = 0.0f;
            #pragma unroll
            for (int c = 0; c < NCLS; ++c) {
                float tt = ((cm >> c) & 1u) ? 1.0f : 0.0f;
                bce += fmaxf(z[c], 0.0f) - z[c] * tt
                     + __logf(1.0f + __expf(-fabsf(z[c])));
            }
            float iou   = iou_scaled(px, py, pw, ph, tx, ty, tw, th, 1.0f);
            float inner = iou_scaled(px, py, pw, ph, tx, ty, tw, th, 0.7f);
            cls_p = bce;  iou_p = 1.0f - iou;  inner_p = 1.0f - inner;  np = 1.0f;
        }
    }

    // Warp shfl reduce, combine the 2 warps in smem.
    #pragma unroll
    for (int o = 16; o > 0; o >>= 1) {
        cls_p   += __shfl_down_sync(0xffffffffu, cls_p,   o);
        iou_p   += __shfl_down_sync(0xffffffffu, iou_p,   o);
        inner_p += __shfl_down_sync(0xffffffffu, inner_p, o);
        np      += __shfl_down_sync(0xffffffffu, np,      o);
    }
    const int warp = tid >> 5;
    if ((tid & 31) == 0) {
        s_red[warp][0] = cls_p;  s_red[warp][1] = iou_p;
        s_red[warp][2] = inner_p; s_red[warp][3] = np;
    }
    __syncthreads();

    // Leader: one vector reduction for all 4 partials, then acq_rel counter
    // chain (release publishes the red; acquire observes all published reds:
    // leader red -> acq_rel d1 -> acq_rel d2 -> final block's reads).
    if (tid == 0) {
        float v0 = s_red[0][0] + s_red[1][0];
        float v1 = s_red[0][1] + s_red[1][1];
        float v2 = s_red[0][2] + s_red[1][2];
        float v3 = s_red[0][3] + s_red[1][3];
        asm volatile("red.global.add.v4.f32 [%0], {%1, %2, %3, %4};"
                     :: "l"(&g_sum[s * 4]), "f"(v0), "f"(v1), "f"(v2), "f"(v3)
                     : "memory");

        int lastflag = 0;
        unsigned d1 = atom_add_acq_rel(&g_done1[b][0], 1u);
        if (d1 == 2u) {                       // batch-last block
            atomicExch(&g_done1[b][0], 0u);   // reset own counter (we are 3rd)
            unsigned d2 = atom_add_acq_rel(&g_done2, 1u);
            lastflag = (d2 == NB - 1);
        }

        if (lastflag) {
            // acq_rel chain complete: the 12 sums are visible (one cache
            // line -> a single round trip).
            float m[12];
            #pragma unroll
            for (int k = 0; k < 12; ++k)
                m[k] = ((const volatile float*)g_sum)[k];

            float cls_total = 0.0f, box_total = 0.0f;
            #pragma unroll
            for (int k2 = 0; k2 < 3; ++k2) {
                float inv = 1.0f / (m[k2 * 4 + 3] + 1e-8f);
                cls_total += m[k2 * 4 + 0] * inv;
                // box = 0.5*iou + 0.5*(0.5*iou + 0.5*inner)
                box_total += 0.75f * (m[k2 * 4 + 1] * inv)
                           + 0.25f * (m[k2 * 4 + 2] * inv);
            }
            cls_total *= (1.0f / 3.0f);
            box_total *= (1.0f / 3.0f);
            out[0] = 0.5f * cls_total + 7.5f * box_total;  // CLS_W, BOX_W
            out[1] = cls_total;
            out[2] = box_total;

            // Reset for next graph replay (kernel-end membar publishes).
            #pragma unroll
            for (int k = 0; k < 12; ++k) g_sum[k] = 0.0f;
            g_done2 = 0u;
        }
    }
}

extern "C" void kernel_launch(void* const* d_in, const int* in_sizes, int n_in,
                              void* d_out, int out_size)
{
    const float* p3   = (const float*)d_in[0];
    const float* p4   = (const float*)d_in[1];
    const float* p5   = (const float*)d_in[2];
    const int*   tcls = (const int*)  d_in[3];
    const float* tbox = (const float*)d_in[4];
    float*       out  = (float*)d_out;

    dim3 grid(NB, 3);
    dl_fused_kernel<<<grid, 64>>>(p3, p4, p5, tcls, tbox, out);
}